// round 12
// baseline (speedup 1.0000x reference)
#include <cuda_runtime.h>
#include <cuda_fp16.h>
#include <cstdint>

#define LVAL 4096
#define NB 64
#define NROWS 16384            // 32*512
#define PW 36                  // padded row stride in u32 words (32 data words + 4 pad)
#define RADIUS 0.9
#define KSPLIT 8

// ---------------- device globals (no allocs allowed) ----------------
__device__ __half g_Bh [NB * LVAL];    // Blaschke hi split, [n][l] l-contig
__device__ __half g_Bl [NB * LVAL];    // lo split
__device__ __half g_BTh[LVAL * NB];    // transposed hi split, [l][n] n-contig
__device__ float  g_proj[KSPLIT * NROWS * NB];   // split-K partial projections
__device__ __half g_W0[NROWS * NB];    // softmax weights hi split, [row][n]
__device__ __half g_W1[NROWS * NB];    // lo split

// ---------------- helpers ----------------
__device__ __forceinline__ unsigned smem_u32p(const void* p) {
    return (unsigned)__cvta_generic_to_shared(p);
}
__device__ __forceinline__ void cp16(unsigned dst, const void* src) {
    asm volatile("cp.async.ca.shared.global [%0], [%1], 16;\n" :: "r"(dst), "l"(src));
}
__device__ __forceinline__ void cp_commit() {
    asm volatile("cp.async.commit_group;\n" ::: "memory");
}
template <int N>
__device__ __forceinline__ void cp_wait() {
    asm volatile("cp.async.wait_group %0;\n" :: "n"(N) : "memory");
}
__device__ __forceinline__ uint32_t packh(__half a, __half b) {
    __half2 h = __halves2half2(a, b);
    return *reinterpret_cast<uint32_t*>(&h);
}
__device__ __forceinline__ uint32_t pack_rn(float a, float b) {
    return packh(__float2half_rn(a), __float2half_rn(b));
}

// D(16x8) += A(16x16) * B(16x8), fp16 inputs, fp32 accum
__device__ __forceinline__ void mma16(float* c, const uint32_t* a, const uint32_t* b) {
    asm volatile(
        "mma.sync.aligned.m16n8k16.row.col.f32.f16.f16.f32 "
        "{%0,%1,%2,%3}, {%4,%5,%6,%7}, {%8,%9}, {%0,%1,%2,%3};\n"
        : "+f"(c[0]), "+f"(c[1]), "+f"(c[2]), "+f"(c[3])
        : "r"(a[0]), "r"(a[1]), "r"(a[2]), "r"(a[3]),
          "r"(b[0]), "r"(b[1]));
}

__device__ __forceinline__ void ldsm_x4(uint32_t* r, uint32_t addr) {
    asm volatile("ldmatrix.sync.aligned.m8n8.x4.shared.b16 {%0,%1,%2,%3}, [%4];"
        : "=r"(r[0]), "=r"(r[1]), "=r"(r[2]), "=r"(r[3]) : "r"(addr));
}

// ---------------- k1: build Blaschke basis + fp16 splits ----------------
__global__ void k1_build() {
    int idx = blockIdx.x * blockDim.x + threadIdx.x;
    if (idx >= NB * LVAL) return;
    int n = idx >> 12;
    int l = idx & 4095;
    const double TWO_PI = 6.283185307179586476925286766559;
    double theta = (double)n * (TWO_PI / 64.0);
    double t     = (double)l * (TWO_PI / 4095.0);   // linspace(0,2pi,4096) incl. endpoint
    float c = cosf((float)(t - theta));             // arg exact in double, cos in fp32
    const float r = (float)RADIUS;
    float v = sqrtf(1.0f - r * r) * (1.0f - r * c) / (1.0f - 2.0f * r * c + r * r);
    __half h = __float2half_rn(v);
    __half lo = __float2half_rn(v - __half2float(h));
    g_Bh [n * LVAL + l] = h;
    g_Bl [n * LVAL + l] = lo;
    g_BTh[l * NB + n]   = h;
}

// ---------------- k2: proj slab GEMM  (split-K = 8, 128-row CTA, ldmatrix frags) ----
// CTA: 128 rows x 64 basis, K-slice 512, 8 chunks of 64, double-buffered.
// stage layout (u32 words): xh[0,4608) xl[4608,9216) bh[9216,11520) bl[11520,13824)
#define K2_STAGE 13824
#define K2_SMEM_BYTES (2 * K2_STAGE * 4)   // 110592

__global__ __launch_bounds__(256, 2) void k2_proj(const float* __restrict__ x) {
    extern __shared__ uint32_t smu[];
    const int tid = threadIdx.x, warp = tid >> 5, lane = tid & 31;
    const int g = lane >> 2, tig = lane & 3;
    const int r0 = blockIdx.x * 128;
    const int kslab = blockIdx.y * (LVAL / KSPLIT);   // 512
    const int rw = (warp & 3) * 32;      // warp x-row offset (A operand, m)
    const int nw = (warp >> 2) * 32;     // warp basis offset (B operand, n)
    const int quad = tid & 15, rloc = tid >> 4;

    const int arow   = lane & 15;
    const int acol16 = (lane >> 4) & 1;
    const int brow   = lane & 7;
    const int bcol16 = (lane >> 3) & 1;
    const int bpair  = (lane >> 4) & 1;

    float acc[8][4];
    #pragma unroll
    for (int i = 0; i < 8; i++)
        #pragma unroll
        for (int j = 0; j < 4; j++) acc[i][j] = 0.f;

    auto stage = [&](int c) {
        uint32_t* b = smu + (c & 1) * K2_STAGE;
        const int kbase = kslab + c * 64;
        #pragma unroll
        for (int j = 0; j < 2; j++) {
            int e = tid + j * 256; int n = e >> 3, seg = e & 7;
            cp16(smem_u32p(b + 9216  + n * PW + seg * 4),
                 g_Bh + (size_t)n * LVAL + kbase + seg * 8);
            cp16(smem_u32p(b + 11520 + n * PW + seg * 4),
                 g_Bl + (size_t)n * LVAL + kbase + seg * 8);
        }
        cp_commit();
        #pragma unroll
        for (int i = 0; i < 8; i++) {
            int row = rloc + i * 16;
            const float4 v = *(const float4*)(x + (size_t)(r0 + row) * LVAL + kbase + quad * 4);
            __half hx = __float2half_rn(v.x), hy = __float2half_rn(v.y);
            __half hz = __float2half_rn(v.z), hw = __float2half_rn(v.w);
            uint32_t h01 = packh(hx, hy), h23 = packh(hz, hw);
            uint32_t l01 = pack_rn(v.x - __half2float(hx), v.y - __half2float(hy));
            uint32_t l23 = pack_rn(v.z - __half2float(hz), v.w - __half2float(hw));
            *(uint2*)(b + row * PW + quad * 2)        = make_uint2(h01, h23);
            *(uint2*)(b + 4608 + row * PW + quad * 2) = make_uint2(l01, l23);
        }
    };

    stage(0);
    for (int c = 0; c < KSPLIT; c++) {
        if (c + 1 < KSPLIT) { stage(c + 1); cp_wait<1>(); }
        else                { cp_wait<0>(); }
        __syncthreads();

        const uint32_t* buf = smu + (c & 1) * K2_STAGE;
        const uint32_t aHi = smem_u32p(buf +        (rw + arow) * PW) + acol16 * 16;
        const uint32_t aLo = smem_u32p(buf + 4608 + (rw + arow) * PW) + acol16 * 16;
        const uint32_t bHi = smem_u32p(buf + 9216  + (nw + bpair * 8 + brow) * PW) + bcol16 * 16;
        const uint32_t bLo = smem_u32p(buf + 11520 + (nw + bpair * 8 + brow) * PW) + bcol16 * 16;

        #pragma unroll
        for (int ks = 0; ks < 4; ks++) {
            const int kb = ks * 32;
            uint32_t ah[2][4], al[2][4], bh[2][4], bl[2][4];
            #pragma unroll
            for (int mt = 0; mt < 2; mt++) {
                ldsm_x4(ah[mt], aHi + mt * (16 * PW * 4) + kb);
                ldsm_x4(al[mt], aLo + mt * (16 * PW * 4) + kb);
            }
            #pragma unroll
            for (int p = 0; p < 2; p++) {
                ldsm_x4(bh[p], bHi + p * (16 * PW * 4) + kb);
                ldsm_x4(bl[p], bLo + p * (16 * PW * 4) + kb);
            }
            #pragma unroll
            for (int mt = 0; mt < 2; mt++)
                #pragma unroll
                for (int nt = 0; nt < 4; nt++) {
                    const int p = nt >> 1, o = (nt & 1) * 2;
                    mma16(acc[mt * 4 + nt], ah[mt], &bh[p][o]);
                    mma16(acc[mt * 4 + nt], ah[mt], &bl[p][o]);
                    mma16(acc[mt * 4 + nt], al[mt], &bh[p][o]);
                }
        }
        __syncthreads();
    }

    float* slab = g_proj + (size_t)blockIdx.y * (NROWS * NB);
    #pragma unroll
    for (int mt = 0; mt < 2; mt++)
        #pragma unroll
        for (int nt = 0; nt < 4; nt++) {
            int col = nw + nt * 8 + 2 * tig;
            int row = r0 + rw + mt * 16 + g;
            const float* cacc = acc[mt * 4 + nt];
            *(float2*)(slab + (size_t)row * NB + col)       = make_float2(cacc[0], cacc[1]);
            *(float2*)(slab + (size_t)(row + 8) * NB + col) = make_float2(cacc[2], cacc[3]);
        }
}

// ---------------- k3: reduce slabs + softmax(|.|) + fp16 W split ----------------
__global__ __launch_bounds__(256) void k3_softmax() {
    const int warp = threadIdx.x >> 5, lane = threadIdx.x & 31;
    const int row = blockIdx.x * 8 + warp;
    const size_t base = (size_t)row * NB + 2 * lane;
    float p0 = 0.f, p1 = 0.f;
    #pragma unroll
    for (int s = 0; s < KSPLIT; s++) {
        float2 v = *(const float2*)(g_proj + (size_t)s * (NROWS * NB) + base);
        p0 += v.x; p1 += v.y;
    }
    float a0 = fabsf(p0), a1 = fabsf(p1);
    float m = fmaxf(a0, a1);
    #pragma unroll
    for (int o = 16; o > 0; o >>= 1) m = fmaxf(m, __shfl_xor_sync(0xffffffffu, m, o));
    float e0 = __expf(a0 - m), e1 = __expf(a1 - m);
    float s = e0 + e1;
    #pragma unroll
    for (int o = 16; o > 0; o >>= 1) s += __shfl_xor_sync(0xffffffffu, s, o);
    float inv = 1.0f / s;
    float w0 = e0 * inv, w1 = e1 * inv;
    __half h0 = __float2half_rn(w0), h1 = __float2half_rn(w1);
    *(uint32_t*)&g_W0[base] = packh(h0, h1);
    *(uint32_t*)&g_W1[base] = pack_rn(w0 - __half2float(h0), w1 - __half2float(h1));
}

// ---------------- k4: out = x + W*B  (64 rows x 128 l per CTA) ----------------
// 2-term: attn = Wh*Bh + Wl*Bh (B plain fp16; W exact hi/lo)
// smem (u32 words): Wh[0,2304) Wl[2304,4608) BTh[4608,9216) xstage[9216,17408)
// epilogue reuses [0,9216) as fp32 attn staging [64][132]
#define K4_SMEM_WORDS 17408
#define K4_SMEM_BYTES (K4_SMEM_WORDS * 4)   // 69632
#define SE 132                 // epilogue staging stride (floats)

__global__ __launch_bounds__(256, 3) void k4_attn(
    const float* __restrict__ x, float* __restrict__ out)
{
    extern __shared__ uint32_t smu[];
    const int tid = threadIdx.x, warp = tid >> 5, lane = tid & 31;
    const int g = lane >> 2, tig = lane & 3;
    const int r0 = blockIdx.y * 64;
    const int l0 = blockIdx.x * 128;
    const int rw = (warp & 1) * 32;      // warp row offset (2 groups of 32)
    const int lw = (warp >> 1) * 32;     // warp l offset   (4 groups of 32)

    // -------- stage W hi/lo (64 rows), BTh (128 rows), and x residual tile --------
    #pragma unroll
    for (int j = 0; j < 2; j++) {
        int e = tid + j * 256; int row = e >> 3, seg = e & 7;
        cp16(smem_u32p(smu + 0    + row * PW + seg * 4), g_W0 + (size_t)(r0 + row) * NB + seg * 8);
        cp16(smem_u32p(smu + 2304 + row * PW + seg * 4), g_W1 + (size_t)(r0 + row) * NB + seg * 8);
    }
    #pragma unroll
    for (int j = 0; j < 4; j++) {
        int e = tid + j * 256; int row = e >> 3, seg = e & 7;
        cp16(smem_u32p(smu + 4608 + row * PW + seg * 4), g_BTh + (size_t)(l0 + row) * NB + seg * 8);
    }
    // x tile: 64 rows x 128 floats, linear rows of 128 words
    #pragma unroll
    for (int j = 0; j < 8; j++) {
        int c = tid + j * 256;            // 2048 chunks of 16B
        int row = c >> 5, off = c & 31;
        cp16(smem_u32p(smu + 9216 + row * 128 + off * 4),
             x + (size_t)(r0 + row) * LVAL + l0 + off * 4);
    }
    cp_commit();
    cp_wait<0>();
    __syncthreads();

    // -------- per-lane ldmatrix base addresses --------
    const int arow   = lane & 15;
    const int acol16 = (lane >> 4) & 1;
    const uint32_t aHi = smem_u32p(smu +        (rw + arow) * PW) + acol16 * 16;
    const uint32_t aLo = smem_u32p(smu + 2304 + (rw + arow) * PW) + acol16 * 16;
    const int brow   = lane & 7;
    const int bcol16 = (lane >> 3) & 1;
    const int bpair  = (lane >> 4) & 1;
    const uint32_t bHi = smem_u32p(smu + 4608 + (lw + bpair * 8 + brow) * PW) + bcol16 * 16;

    float acc[8][4];
    #pragma unroll
    for (int i = 0; i < 8; i++)
        #pragma unroll
        for (int j = 0; j < 4; j++) acc[i][j] = 0.f;

    #pragma unroll
    for (int ks = 0; ks < 4; ks++) {
        const int kb = ks * 32;
        uint32_t ah[2][4], al[2][4], bh[2][4];
        #pragma unroll
        for (int mt = 0; mt < 2; mt++) {
            ldsm_x4(ah[mt], aHi + mt * (16 * PW * 4) + kb);
            ldsm_x4(al[mt], aLo + mt * (16 * PW * 4) + kb);
        }
        #pragma unroll
        for (int p = 0; p < 2; p++)
            ldsm_x4(bh[p], bHi + p * (16 * PW * 4) + kb);
        #pragma unroll
        for (int mt = 0; mt < 2; mt++)
            #pragma unroll
            for (int nt = 0; nt < 4; nt++) {
                const int p = nt >> 1, o = (nt & 1) * 2;
                mma16(acc[mt * 4 + nt], ah[mt], &bh[p][o]);
                mma16(acc[mt * 4 + nt], al[mt], &bh[p][o]);
            }
    }

    // -------- epilogue: attn -> smem staging, then smem-only out = x + attn --------
    __syncthreads();                      // done reading W/BTh smem
    float* smf = (float*)smu;             // overlays [0,9216): attn [64][132]
    const float* smx = (const float*)(smu + 9216);   // x tile [64][128]
    #pragma unroll
    for (int mt = 0; mt < 2; mt++)
        #pragma unroll
        for (int nt = 0; nt < 4; nt++) {
            int row = rw + mt * 16 + g;
            int col = lw + nt * 8 + 2 * tig;
            const float* c = acc[mt * 4 + nt];
            *(float2*)(smf + row * SE + col)       = make_float2(c[0], c[1]);
            *(float2*)(smf + (row + 8) * SE + col) = make_float2(c[2], c[3]);
        }
    __syncthreads();

    #pragma unroll
    for (int pass = 0; pass < 8; pass++) {
        int row = pass * 8 + warp;
        int col = lane * 4;
        float4 a = *(const float4*)(smf + row * SE + col);
        float4 xv = *(const float4*)(smx + row * 128 + col);
        size_t gi = (size_t)(r0 + row) * LVAL + l0 + col;
        *(float4*)(out + gi) =
            make_float4(xv.x + a.x, xv.y + a.y, xv.z + a.z, xv.w + a.w);
    }
}

// ---------------- launch ----------------
extern "C" void kernel_launch(void* const* d_in, const int* in_sizes, int n_in,
                              void* d_out, int out_size) {
    const float* x = (const float*)d_in[0];
    float* out = (float*)d_out;
    (void)in_sizes; (void)n_in; (void)out_size;

    static bool attr_done = false;
    if (!attr_done) {
        cudaFuncSetAttribute(k2_proj, cudaFuncAttributeMaxDynamicSharedMemorySize, K2_SMEM_BYTES);
        cudaFuncSetAttribute(k4_attn, cudaFuncAttributeMaxDynamicSharedMemorySize, K4_SMEM_BYTES);
        attr_done = true;
    }

    k1_build<<<(NB * LVAL + 255) / 256, 256>>>();
    k2_proj<<<dim3(NROWS / 128, KSPLIT), 256, K2_SMEM_BYTES>>>(x);
    k3_softmax<<<NROWS / 8, 256>>>();
    k4_attn<<<dim3(LVAL / 128, NROWS / 64), 256, K4_SMEM_BYTES>>>(x, out);
}

// round 13
// speedup vs baseline: 1.1832x; 1.1832x over previous
#include <cuda_runtime.h>
#include <cuda_fp16.h>
#include <cstdint>

#define LVAL 4096
#define NB 64
#define NROWS 16384            // 32*512
#define PW 36                  // padded row stride in u32 words (32 data words + 4 pad)
#define RADIUS 0.9
#define KSPLIT 8

// ---------------- device globals (no allocs allowed) ----------------
__device__ __half g_Bh [NB * LVAL];    // Blaschke hi split, [n][l] l-contig
__device__ __half g_Bl [NB * LVAL];    // lo split
__device__ __half g_BTh[LVAL * NB];    // transposed hi (plain fp16 B for attn GEMM)
__device__ float  g_proj[KSPLIT * NROWS * NB];   // split-K partial projections
__device__ __half g_W0[NROWS * NB];    // softmax weights hi split, [row][n]
__device__ __half g_W1[NROWS * NB];    // lo split

// ---------------- helpers ----------------
__device__ __forceinline__ unsigned smem_u32p(const void* p) {
    return (unsigned)__cvta_generic_to_shared(p);
}
__device__ __forceinline__ void cp16(unsigned dst, const void* src) {
    asm volatile("cp.async.ca.shared.global [%0], [%1], 16;\n" :: "r"(dst), "l"(src));
}
__device__ __forceinline__ void cp_commit() {
    asm volatile("cp.async.commit_group;\n" ::: "memory");
}
template <int N>
__device__ __forceinline__ void cp_wait() {
    asm volatile("cp.async.wait_group %0;\n" :: "n"(N) : "memory");
}
__device__ __forceinline__ uint32_t packh(__half a, __half b) {
    __half2 h = __halves2half2(a, b);
    return *reinterpret_cast<uint32_t*>(&h);
}
__device__ __forceinline__ uint32_t pack_rn(float a, float b) {
    return packh(__float2half_rn(a), __float2half_rn(b));
}

// D(16x8) += A(16x16) * B(16x8), fp16 inputs, fp32 accum
__device__ __forceinline__ void mma16(float* c, const uint32_t* a, const uint32_t* b) {
    asm volatile(
        "mma.sync.aligned.m16n8k16.row.col.f32.f16.f16.f32 "
        "{%0,%1,%2,%3}, {%4,%5,%6,%7}, {%8,%9}, {%0,%1,%2,%3};\n"
        : "+f"(c[0]), "+f"(c[1]), "+f"(c[2]), "+f"(c[3])
        : "r"(a[0]), "r"(a[1]), "r"(a[2]), "r"(a[3]),
          "r"(b[0]), "r"(b[1]));
}

__device__ __forceinline__ void ldsm_x4(uint32_t* r, uint32_t addr) {
    asm volatile("ldmatrix.sync.aligned.m8n8.x4.shared.b16 {%0,%1,%2,%3}, [%4];"
        : "=r"(r[0]), "=r"(r[1]), "=r"(r[2]), "=r"(r[3]) : "r"(addr));
}

// ---------------- k1: build Blaschke basis + fp16 splits ----------------
__global__ void k1_build() {
    int idx = blockIdx.x * blockDim.x + threadIdx.x;
    if (idx >= NB * LVAL) return;
    int n = idx >> 12;
    int l = idx & 4095;
    const double TWO_PI = 6.283185307179586476925286766559;
    double theta = (double)n * (TWO_PI / 64.0);
    double t     = (double)l * (TWO_PI / 4095.0);   // linspace(0,2pi,4096) incl. endpoint
    float c = cosf((float)(t - theta));             // arg exact in double, cos in fp32
    const float r = (float)RADIUS;
    float v = sqrtf(1.0f - r * r) * (1.0f - r * c) / (1.0f - 2.0f * r * c + r * r);
    __half h = __float2half_rn(v);
    __half lo = __float2half_rn(v - __half2float(h));
    g_Bh [n * LVAL + l] = h;
    g_Bl [n * LVAL + l] = lo;
    g_BTh[l * NB + n]   = h;
}

// ---------------- k2: proj slab GEMM  (split-K = 8, 128-row CTA, ldmatrix frags) ----
// CTA: 128 rows x 64 basis, K-slice 512, 8 chunks of 64, double-buffered.
// stage layout (u32 words): xh[0,4608) xl[4608,9216) bh[9216,11520) bl[11520,13824)
#define K2_STAGE 13824
#define K2_SMEM_BYTES (2 * K2_STAGE * 4)   // 110592

__global__ __launch_bounds__(256, 2) void k2_proj(const float* __restrict__ x) {
    extern __shared__ uint32_t smu[];
    const int tid = threadIdx.x, warp = tid >> 5, lane = tid & 31;
    const int g = lane >> 2, tig = lane & 3;
    const int r0 = blockIdx.x * 128;
    const int kslab = blockIdx.y * (LVAL / KSPLIT);   // 512
    const int rw = (warp & 3) * 32;      // warp x-row offset (A operand, m)
    const int nw = (warp >> 2) * 32;     // warp basis offset (B operand, n)
    const int quad = tid & 15, rloc = tid >> 4;

    const int arow   = lane & 15;
    const int acol16 = (lane >> 4) & 1;
    const int brow   = lane & 7;
    const int bcol16 = (lane >> 3) & 1;
    const int bpair  = (lane >> 4) & 1;

    float acc[8][4];
    #pragma unroll
    for (int i = 0; i < 8; i++)
        #pragma unroll
        for (int j = 0; j < 4; j++) acc[i][j] = 0.f;

    auto stage = [&](int c) {
        uint32_t* b = smu + (c & 1) * K2_STAGE;
        const int kbase = kslab + c * 64;
        #pragma unroll
        for (int j = 0; j < 2; j++) {
            int e = tid + j * 256; int n = e >> 3, seg = e & 7;
            cp16(smem_u32p(b + 9216  + n * PW + seg * 4),
                 g_Bh + (size_t)n * LVAL + kbase + seg * 8);
            cp16(smem_u32p(b + 11520 + n * PW + seg * 4),
                 g_Bl + (size_t)n * LVAL + kbase + seg * 8);
        }
        cp_commit();
        #pragma unroll
        for (int i = 0; i < 8; i++) {
            int row = rloc + i * 16;
            const float4 v = *(const float4*)(x + (size_t)(r0 + row) * LVAL + kbase + quad * 4);
            __half hx = __float2half_rn(v.x), hy = __float2half_rn(v.y);
            __half hz = __float2half_rn(v.z), hw = __float2half_rn(v.w);
            uint32_t h01 = packh(hx, hy), h23 = packh(hz, hw);
            uint32_t l01 = pack_rn(v.x - __half2float(hx), v.y - __half2float(hy));
            uint32_t l23 = pack_rn(v.z - __half2float(hz), v.w - __half2float(hw));
            *(uint2*)(b + row * PW + quad * 2)        = make_uint2(h01, h23);
            *(uint2*)(b + 4608 + row * PW + quad * 2) = make_uint2(l01, l23);
        }
    };

    stage(0);
    for (int c = 0; c < KSPLIT; c++) {
        if (c + 1 < KSPLIT) { stage(c + 1); cp_wait<1>(); }
        else                { cp_wait<0>(); }
        __syncthreads();

        const uint32_t* buf = smu + (c & 1) * K2_STAGE;
        const uint32_t aHi = smem_u32p(buf +        (rw + arow) * PW) + acol16 * 16;
        const uint32_t aLo = smem_u32p(buf + 4608 + (rw + arow) * PW) + acol16 * 16;
        const uint32_t bHi = smem_u32p(buf + 9216  + (nw + bpair * 8 + brow) * PW) + bcol16 * 16;
        const uint32_t bLo = smem_u32p(buf + 11520 + (nw + bpair * 8 + brow) * PW) + bcol16 * 16;

        #pragma unroll
        for (int ks = 0; ks < 4; ks++) {
            const int kb = ks * 32;
            uint32_t ah[2][4], al[2][4], bh[2][4], bl[2][4];
            #pragma unroll
            for (int mt = 0; mt < 2; mt++) {
                ldsm_x4(ah[mt], aHi + mt * (16 * PW * 4) + kb);
                ldsm_x4(al[mt], aLo + mt * (16 * PW * 4) + kb);
            }
            #pragma unroll
            for (int p = 0; p < 2; p++) {
                ldsm_x4(bh[p], bHi + p * (16 * PW * 4) + kb);
                ldsm_x4(bl[p], bLo + p * (16 * PW * 4) + kb);
            }
            #pragma unroll
            for (int mt = 0; mt < 2; mt++)
                #pragma unroll
                for (int nt = 0; nt < 4; nt++) {
                    const int p = nt >> 1, o = (nt & 1) * 2;
                    mma16(acc[mt * 4 + nt], ah[mt], &bh[p][o]);
                    mma16(acc[mt * 4 + nt], ah[mt], &bl[p][o]);
                    mma16(acc[mt * 4 + nt], al[mt], &bh[p][o]);
                }
        }
        __syncthreads();
    }

    float* slab = g_proj + (size_t)blockIdx.y * (NROWS * NB);
    #pragma unroll
    for (int mt = 0; mt < 2; mt++)
        #pragma unroll
        for (int nt = 0; nt < 4; nt++) {
            int col = nw + nt * 8 + 2 * tig;
            int row = r0 + rw + mt * 16 + g;
            const float* cacc = acc[mt * 4 + nt];
            *(float2*)(slab + (size_t)row * NB + col)       = make_float2(cacc[0], cacc[1]);
            *(float2*)(slab + (size_t)(row + 8) * NB + col) = make_float2(cacc[2], cacc[3]);
        }
}

// ---------------- k3: reduce slabs + softmax(|.|) + fp16 W split ----------------
__global__ __launch_bounds__(256) void k3_softmax() {
    const int warp = threadIdx.x >> 5, lane = threadIdx.x & 31;
    const int row = blockIdx.x * 8 + warp;
    const size_t base = (size_t)row * NB + 2 * lane;
    float p0 = 0.f, p1 = 0.f;
    #pragma unroll
    for (int s = 0; s < KSPLIT; s++) {
        float2 v = *(const float2*)(g_proj + (size_t)s * (NROWS * NB) + base);
        p0 += v.x; p1 += v.y;
    }
    float a0 = fabsf(p0), a1 = fabsf(p1);
    float m = fmaxf(a0, a1);
    #pragma unroll
    for (int o = 16; o > 0; o >>= 1) m = fmaxf(m, __shfl_xor_sync(0xffffffffu, m, o));
    float e0 = __expf(a0 - m), e1 = __expf(a1 - m);
    float s = e0 + e1;
    #pragma unroll
    for (int o = 16; o > 0; o >>= 1) s += __shfl_xor_sync(0xffffffffu, s, o);
    float inv = 1.0f / s;
    float w0 = e0 * inv, w1 = e1 * inv;
    __half h0 = __float2half_rn(w0), h1 = __float2half_rn(w1);
    *(uint32_t*)&g_W0[base] = packh(h0, h1);
    *(uint32_t*)&g_W1[base] = pack_rn(w0 - __half2float(h0), w1 - __half2float(h1));
}

// ---------------- k4: out = x + W*B  (64 rows x 128 l per CTA, 2-term) ----------------
// attn = (Wh + Wl) * Bh ; W split exact, B plain fp16 (validated rel_err 1.3e-4)
// smem (u32 words): Wh[0,2304) Wl[2304,4608) BTh[4608,9216)
// epilogue reuses smem as fp32 attn staging [64][132] (8448 words < 9216)
#define K4_SMEM_WORDS 9216
#define K4_SMEM_BYTES (K4_SMEM_WORDS * 4)   // 36864
#define SE 132                 // epilogue staging stride (floats)

__global__ __launch_bounds__(256, 4) void k4_attn(
    const float* __restrict__ x, float* __restrict__ out)
{
    extern __shared__ uint32_t smu[];
    const int tid = threadIdx.x, warp = tid >> 5, lane = tid & 31;
    const int g = lane >> 2, tig = lane & 3;
    const int r0 = blockIdx.y * 64;
    const int l0 = blockIdx.x * 128;
    const int rw = (warp & 1) * 32;      // warp row offset (2 groups of 32)
    const int lw = (warp >> 1) * 32;     // warp l offset   (4 groups of 32)

    // -------- stage W hi/lo (64 rows) and BTh (128 rows) via cp.async --------
    #pragma unroll
    for (int j = 0; j < 2; j++) {
        int e = tid + j * 256; int row = e >> 3, seg = e & 7;
        cp16(smem_u32p(smu + 0    + row * PW + seg * 4), g_W0 + (size_t)(r0 + row) * NB + seg * 8);
        cp16(smem_u32p(smu + 2304 + row * PW + seg * 4), g_W1 + (size_t)(r0 + row) * NB + seg * 8);
    }
    #pragma unroll
    for (int j = 0; j < 4; j++) {
        int e = tid + j * 256; int row = e >> 3, seg = e & 7;
        cp16(smem_u32p(smu + 4608 + row * PW + seg * 4), g_BTh + (size_t)(l0 + row) * NB + seg * 8);
    }
    cp_commit();
    cp_wait<0>();
    __syncthreads();

    // -------- per-lane ldmatrix base addresses --------
    const int arow   = lane & 15;
    const int acol16 = (lane >> 4) & 1;
    const uint32_t aHi = smem_u32p(smu +        (rw + arow) * PW) + acol16 * 16;
    const uint32_t aLo = smem_u32p(smu + 2304 + (rw + arow) * PW) + acol16 * 16;
    const int brow   = lane & 7;
    const int bcol16 = (lane >> 3) & 1;
    const int bpair  = (lane >> 4) & 1;
    const uint32_t bHi = smem_u32p(smu + 4608 + (lw + bpair * 8 + brow) * PW) + bcol16 * 16;

    float acc[8][4];
    #pragma unroll
    for (int i = 0; i < 8; i++)
        #pragma unroll
        for (int j = 0; j < 4; j++) acc[i][j] = 0.f;

    #pragma unroll
    for (int ks = 0; ks < 4; ks++) {
        const int kb = ks * 32;
        uint32_t ah[2][4], al[2][4], bh[2][4];
        #pragma unroll
        for (int mt = 0; mt < 2; mt++) {
            ldsm_x4(ah[mt], aHi + mt * (16 * PW * 4) + kb);
            ldsm_x4(al[mt], aLo + mt * (16 * PW * 4) + kb);
        }
        #pragma unroll
        for (int p = 0; p < 2; p++)
            ldsm_x4(bh[p], bHi + p * (16 * PW * 4) + kb);
        #pragma unroll
        for (int mt = 0; mt < 2; mt++)
            #pragma unroll
            for (int nt = 0; nt < 4; nt++) {
                const int p = nt >> 1, o = (nt & 1) * 2;
                mma16(acc[mt * 4 + nt], ah[mt], &bh[p][o]);
                mma16(acc[mt * 4 + nt], al[mt], &bh[p][o]);
            }
    }

    // -------- epilogue: attn -> smem staging, then coalesced out = x + attn --------
    __syncthreads();                      // everyone done reading W/BTh smem
    float* smf = (float*)smu;
    #pragma unroll
    for (int mt = 0; mt < 2; mt++)
        #pragma unroll
        for (int nt = 0; nt < 4; nt++) {
            int row = rw + mt * 16 + g;
            int col = lw + nt * 8 + 2 * tig;
            const float* c = acc[mt * 4 + nt];
            *(float2*)(smf + row * SE + col)       = make_float2(c[0], c[1]);
            *(float2*)(smf + (row + 8) * SE + col) = make_float2(c[2], c[3]);
        }
    __syncthreads();

    #pragma unroll
    for (int pass = 0; pass < 8; pass++) {
        int row = pass * 8 + warp;
        int col = lane * 4;
        float4 a = *(const float4*)(smf + row * SE + col);
        size_t gi = (size_t)(r0 + row) * LVAL + l0 + col;
        float4 xv = *(const float4*)(x + gi);
        *(float4*)(out + gi) =
            make_float4(xv.x + a.x, xv.y + a.y, xv.z + a.z, xv.w + a.w);
    }
}

// ---------------- launch ----------------
extern "C" void kernel_launch(void* const* d_in, const int* in_sizes, int n_in,
                              void* d_out, int out_size) {
    const float* x = (const float*)d_in[0];
    float* out = (float*)d_out;
    (void)in_sizes; (void)n_in; (void)out_size;

    static bool attr_done = false;
    if (!attr_done) {
        cudaFuncSetAttribute(k2_proj, cudaFuncAttributeMaxDynamicSharedMemorySize, K2_SMEM_BYTES);
        cudaFuncSetAttribute(k4_attn, cudaFuncAttributeMaxDynamicSharedMemorySize, K4_SMEM_BYTES);
        attr_done = true;
    }

    k1_build<<<(NB * LVAL + 255) / 256, 256>>>();
    k2_proj<<<dim3(NROWS / 128, KSPLIT), 256, K2_SMEM_BYTES>>>(x);
    k3_softmax<<<NROWS / 8, 256>>>();
    k4_attn<<<dim3(LVAL / 128, NROWS / 64), 256, K4_SMEM_BYTES>>>(x, out);
}

// round 14
// speedup vs baseline: 1.2354x; 1.0441x over previous
#include <cuda_runtime.h>
#include <cuda_fp16.h>
#include <cstdint>

#define LVAL 4096
#define NB 64
#define NROWS 16384            // 32*512
#define PW 36                  // padded row stride in u32 words (32 data words + 4 pad)
#define RADIUS 0.9
#define KSPLIT 8

// ---------------- device globals (no allocs allowed) ----------------
__device__ __half g_Bh [NB * LVAL];    // Blaschke hi split, [n][l] l-contig
__device__ __half g_Bl [NB * LVAL];    // lo split
__device__ __half g_BTh[LVAL * NB];    // transposed (plain fp16 B for attn GEMM)
__device__ float  g_proj[KSPLIT * NROWS * NB];   // split-K partial projections
__device__ __half g_W[NROWS * NB];     // softmax weights, plain fp16, [row][n]

// ---------------- helpers ----------------
__device__ __forceinline__ unsigned smem_u32p(const void* p) {
    return (unsigned)__cvta_generic_to_shared(p);
}
__device__ __forceinline__ void cp16(unsigned dst, const void* src) {
    asm volatile("cp.async.ca.shared.global [%0], [%1], 16;\n" :: "r"(dst), "l"(src));
}
__device__ __forceinline__ void cp_commit() {
    asm volatile("cp.async.commit_group;\n" ::: "memory");
}
template <int N>
__device__ __forceinline__ void cp_wait() {
    asm volatile("cp.async.wait_group %0;\n" :: "n"(N) : "memory");
}
__device__ __forceinline__ uint32_t packh(__half a, __half b) {
    __half2 h = __halves2half2(a, b);
    return *reinterpret_cast<uint32_t*>(&h);
}
__device__ __forceinline__ uint32_t pack_rn(float a, float b) {
    return packh(__float2half_rn(a), __float2half_rn(b));
}

// D(16x8) += A(16x16) * B(16x8), fp16 inputs, fp32 accum
__device__ __forceinline__ void mma16(float* c, const uint32_t* a, const uint32_t* b) {
    asm volatile(
        "mma.sync.aligned.m16n8k16.row.col.f32.f16.f16.f32 "
        "{%0,%1,%2,%3}, {%4,%5,%6,%7}, {%8,%9}, {%0,%1,%2,%3};\n"
        : "+f"(c[0]), "+f"(c[1]), "+f"(c[2]), "+f"(c[3])
        : "r"(a[0]), "r"(a[1]), "r"(a[2]), "r"(a[3]),
          "r"(b[0]), "r"(b[1]));
}

__device__ __forceinline__ void ldsm_x4(uint32_t* r, uint32_t addr) {
    asm volatile("ldmatrix.sync.aligned.m8n8.x4.shared.b16 {%0,%1,%2,%3}, [%4];"
        : "=r"(r[0]), "=r"(r[1]), "=r"(r[2]), "=r"(r[3]) : "r"(addr));
}

// ---------------- k1: build Blaschke basis + fp16 splits ----------------
__global__ void k1_build() {
    int idx = blockIdx.x * blockDim.x + threadIdx.x;
    if (idx >= NB * LVAL) return;
    int n = idx >> 12;
    int l = idx & 4095;
    const double TWO_PI = 6.283185307179586476925286766559;
    double theta = (double)n * (TWO_PI / 64.0);
    double t     = (double)l * (TWO_PI / 4095.0);   // linspace(0,2pi,4096) incl. endpoint
    float c = cosf((float)(t - theta));             // arg exact in double, cos in fp32
    const float r = (float)RADIUS;
    float v = sqrtf(1.0f - r * r) * (1.0f - r * c) / (1.0f - 2.0f * r * c + r * r);
    __half h = __float2half_rn(v);
    __half lo = __float2half_rn(v - __half2float(h));
    g_Bh [n * LVAL + l] = h;
    g_Bl [n * LVAL + l] = lo;
    g_BTh[l * NB + n]   = h;
}

// ---------------- k2: proj slab GEMM  (split-K = 8, 128-row CTA, pipelined) ----
// CTA: 128 rows x 64 basis, K-slice 512, 8 chunks of 64, double-buffered.
// stage layout (u32 words): xh[0,4608) xl[4608,9216) bh[9216,11520) bl[11520,13824)
// Pipeline: at iter c (after sync): issue B cp.async for c+1; mma(c) overlaps the
// in-flight B load and the x LDGs issued last iteration; then cvt+STS x_{c+1}.
#define K2_STAGE 13824
#define K2_SMEM_BYTES (2 * K2_STAGE * 4)   // 110592

__global__ __launch_bounds__(256, 2) void k2_proj(const float* __restrict__ x) {
    extern __shared__ uint32_t smu[];
    const int tid = threadIdx.x, warp = tid >> 5, lane = tid & 31;
    const int g = lane >> 2, tig = lane & 3;
    const int r0 = blockIdx.x * 128;
    const int kslab = blockIdx.y * (LVAL / KSPLIT);   // 512
    const int rw = (warp & 3) * 32;      // warp x-row offset (A operand, m)
    const int nw = (warp >> 2) * 32;     // warp basis offset (B operand, n)
    const int quad = tid & 15, rloc = tid >> 4;

    const int arow   = lane & 15;
    const int acol16 = (lane >> 4) & 1;
    const int brow   = lane & 7;
    const int bcol16 = (lane >> 3) & 1;
    const int bpair  = (lane >> 4) & 1;

    float acc[8][4];
    #pragma unroll
    for (int i = 0; i < 8; i++)
        #pragma unroll
        for (int j = 0; j < 4; j++) acc[i][j] = 0.f;

    auto ldg_x = [&](int c, float4* xr) {
        const int kbase = kslab + c * 64;
        #pragma unroll
        for (int i = 0; i < 8; i++) {
            int row = rloc + i * 16;
            xr[i] = *(const float4*)(x + (size_t)(r0 + row) * LVAL + kbase + quad * 4);
        }
    };
    auto cvt_sts_x = [&](int c, const float4* xr) {
        uint32_t* b = smu + (c & 1) * K2_STAGE;
        #pragma unroll
        for (int i = 0; i < 8; i++) {
            int row = rloc + i * 16;
            const float4 v = xr[i];
            __half hx = __float2half_rn(v.x), hy = __float2half_rn(v.y);
            __half hz = __float2half_rn(v.z), hw = __float2half_rn(v.w);
            uint32_t h01 = packh(hx, hy), h23 = packh(hz, hw);
            uint32_t l01 = pack_rn(v.x - __half2float(hx), v.y - __half2float(hy));
            uint32_t l23 = pack_rn(v.z - __half2float(hz), v.w - __half2float(hw));
            *(uint2*)(b + row * PW + quad * 2)        = make_uint2(h01, h23);
            *(uint2*)(b + 4608 + row * PW + quad * 2) = make_uint2(l01, l23);
        }
    };
    auto cp_B = [&](int c) {
        uint32_t* b = smu + (c & 1) * K2_STAGE;
        const int kbase = kslab + c * 64;
        #pragma unroll
        for (int j = 0; j < 2; j++) {
            int e = tid + j * 256; int n = e >> 3, seg = e & 7;
            cp16(smem_u32p(b + 9216  + n * PW + seg * 4),
                 g_Bh + (size_t)n * LVAL + kbase + seg * 8);
            cp16(smem_u32p(b + 11520 + n * PW + seg * 4),
                 g_Bl + (size_t)n * LVAL + kbase + seg * 8);
        }
        cp_commit();
    };

    float4 xr[8];
    // prologue: B0 in flight; x0 converted; x1 loaded into regs
    cp_B(0);
    ldg_x(0, xr);
    cvt_sts_x(0, xr);
    ldg_x(1, xr);

    for (int c = 0; c < KSPLIT; c++) {
        cp_wait<0>();          // B_c landed
        __syncthreads();       // orders STS x_c (prev iter) + frees buf (c+1)&1
        if (c + 1 < KSPLIT) cp_B(c + 1);   // overlaps mma(c)

        const uint32_t* buf = smu + (c & 1) * K2_STAGE;
        const uint32_t aHi = smem_u32p(buf +        (rw + arow) * PW) + acol16 * 16;
        const uint32_t aLo = smem_u32p(buf + 4608 + (rw + arow) * PW) + acol16 * 16;
        const uint32_t bHi = smem_u32p(buf + 9216  + (nw + bpair * 8 + brow) * PW) + bcol16 * 16;
        const uint32_t bLo = smem_u32p(buf + 11520 + (nw + bpair * 8 + brow) * PW) + bcol16 * 16;

        #pragma unroll
        for (int ks = 0; ks < 4; ks++) {
            const int kb = ks * 32;
            uint32_t ah[2][4], al[2][4], bh[2][4], bl[2][4];
            #pragma unroll
            for (int mt = 0; mt < 2; mt++) {
                ldsm_x4(ah[mt], aHi + mt * (16 * PW * 4) + kb);
                ldsm_x4(al[mt], aLo + mt * (16 * PW * 4) + kb);
            }
            #pragma unroll
            for (int p = 0; p < 2; p++) {
                ldsm_x4(bh[p], bHi + p * (16 * PW * 4) + kb);
                ldsm_x4(bl[p], bLo + p * (16 * PW * 4) + kb);
            }
            #pragma unroll
            for (int mt = 0; mt < 2; mt++)
                #pragma unroll
                for (int nt = 0; nt < 4; nt++) {
                    const int p = nt >> 1, o = (nt & 1) * 2;
                    mma16(acc[mt * 4 + nt], ah[mt], &bh[p][o]);
                    mma16(acc[mt * 4 + nt], ah[mt], &bl[p][o]);
                    mma16(acc[mt * 4 + nt], al[mt], &bh[p][o]);
                }
        }

        if (c + 1 < KSPLIT) {
            cvt_sts_x(c + 1, xr);            // regs loaded last iteration
            if (c + 2 < KSPLIT) ldg_x(c + 2, xr);   // hidden behind next mma
        }
    }

    float* slab = g_proj + (size_t)blockIdx.y * (NROWS * NB);
    #pragma unroll
    for (int mt = 0; mt < 2; mt++)
        #pragma unroll
        for (int nt = 0; nt < 4; nt++) {
            int col = nw + nt * 8 + 2 * tig;
            int row = r0 + rw + mt * 16 + g;
            const float* cacc = acc[mt * 4 + nt];
            *(float2*)(slab + (size_t)row * NB + col)       = make_float2(cacc[0], cacc[1]);
            *(float2*)(slab + (size_t)(row + 8) * NB + col) = make_float2(cacc[2], cacc[3]);
        }
}

// ---------------- k3: reduce slabs + softmax(|.|) + fp16 W ----------------
__global__ __launch_bounds__(256) void k3_softmax() {
    const int warp = threadIdx.x >> 5, lane = threadIdx.x & 31;
    const int row = blockIdx.x * 8 + warp;
    const size_t base = (size_t)row * NB + 2 * lane;
    float p0 = 0.f, p1 = 0.f;
    #pragma unroll
    for (int s = 0; s < KSPLIT; s++) {
        float2 v = *(const float2*)(g_proj + (size_t)s * (NROWS * NB) + base);
        p0 += v.x; p1 += v.y;
    }
    float a0 = fabsf(p0), a1 = fabsf(p1);
    float m = fmaxf(a0, a1);
    #pragma unroll
    for (int o = 16; o > 0; o >>= 1) m = fmaxf(m, __shfl_xor_sync(0xffffffffu, m, o));
    float e0 = __expf(a0 - m), e1 = __expf(a1 - m);
    float s = e0 + e1;
    #pragma unroll
    for (int o = 16; o > 0; o >>= 1) s += __shfl_xor_sync(0xffffffffu, s, o);
    float inv = 1.0f / s;
    *(uint32_t*)&g_W[base] = pack_rn(e0 * inv, e1 * inv);
}

// ---------------- k4: out = x + W*B  (64 rows x 128 l per CTA, single-term) --------
// attn = W * Bh, both plain fp16 (W rounding ~1.3e-4, B rounding ~1.3e-4, RSS ~1.8e-4)
// smem (u32 words): W[0,2304) BTh[2304,6912); epilogue staging [64][132] = 8448 words
#define K4_SMEM_WORDS 8448
#define K4_SMEM_BYTES (K4_SMEM_WORDS * 4)   // 33792
#define SE 132                 // epilogue staging stride (floats)

__global__ __launch_bounds__(256, 4) void k4_attn(
    const float* __restrict__ x, float* __restrict__ out)
{
    extern __shared__ uint32_t smu[];
    const int tid = threadIdx.x, warp = tid >> 5, lane = tid & 31;
    const int g = lane >> 2, tig = lane & 3;
    const int r0 = blockIdx.y * 64;
    const int l0 = blockIdx.x * 128;
    const int rw = (warp & 1) * 32;      // warp row offset (2 groups of 32)
    const int lw = (warp >> 1) * 32;     // warp l offset   (4 groups of 32)

    // -------- stage W (64 rows) and BTh (128 rows) via cp.async --------
    #pragma unroll
    for (int j = 0; j < 2; j++) {
        int e = tid + j * 256; int row = e >> 3, seg = e & 7;
        cp16(smem_u32p(smu + row * PW + seg * 4), g_W + (size_t)(r0 + row) * NB + seg * 8);
    }
    #pragma unroll
    for (int j = 0; j < 4; j++) {
        int e = tid + j * 256; int row = e >> 3, seg = e & 7;
        cp16(smem_u32p(smu + 2304 + row * PW + seg * 4), g_BTh + (size_t)(l0 + row) * NB + seg * 8);
    }
    cp_commit();
    cp_wait<0>();
    __syncthreads();

    // -------- per-lane ldmatrix base addresses --------
    const int arow   = lane & 15;
    const int acol16 = (lane >> 4) & 1;
    const uint32_t aW = smem_u32p(smu + (rw + arow) * PW) + acol16 * 16;
    const int brow   = lane & 7;
    const int bcol16 = (lane >> 3) & 1;
    const int bpair  = (lane >> 4) & 1;
    const uint32_t bB = smem_u32p(smu + 2304 + (lw + bpair * 8 + brow) * PW) + bcol16 * 16;

    float acc[8][4];
    #pragma unroll
    for (int i = 0; i < 8; i++)
        #pragma unroll
        for (int j = 0; j < 4; j++) acc[i][j] = 0.f;

    #pragma unroll
    for (int ks = 0; ks < 4; ks++) {
        const int kb = ks * 32;
        uint32_t ah[2][4], bh[2][4];
        #pragma unroll
        for (int mt = 0; mt < 2; mt++)
            ldsm_x4(ah[mt], aW + mt * (16 * PW * 4) + kb);
        #pragma unroll
        for (int p = 0; p < 2; p++)
            ldsm_x4(bh[p], bB + p * (16 * PW * 4) + kb);
        #pragma unroll
        for (int mt = 0; mt < 2; mt++)
            #pragma unroll
            for (int nt = 0; nt < 4; nt++) {
                const int p = nt >> 1, o = (nt & 1) * 2;
                mma16(acc[mt * 4 + nt], ah[mt], &bh[p][o]);
            }
    }

    // -------- epilogue: attn -> smem staging, then coalesced out = x + attn --------
    __syncthreads();                      // everyone done reading W/BTh smem
    float* smf = (float*)smu;
    #pragma unroll
    for (int mt = 0; mt < 2; mt++)
        #pragma unroll
        for (int nt = 0; nt < 4; nt++) {
            int row = rw + mt * 16 + g;
            int col = lw + nt * 8 + 2 * tig;
            const float* c = acc[mt * 4 + nt];
            *(float2*)(smf + row * SE + col)       = make_float2(c[0], c[1]);
            *(float2*)(smf + (row + 8) * SE + col) = make_float2(c[2], c[3]);
        }
    __syncthreads();

    #pragma unroll
    for (int pass = 0; pass < 8; pass++) {
        int row = pass * 8 + warp;
        int col = lane * 4;
        float4 a = *(const float4*)(smf + row * SE + col);
        size_t gi = (size_t)(r0 + row) * LVAL + l0 + col;
        float4 xv = *(const float4*)(x + gi);
        *(float4*)(out + gi) =
            make_float4(xv.x + a.x, xv.y + a.y, xv.z + a.z, xv.w + a.w);
    }
}

// ---------------- launch ----------------
extern "C" void kernel_launch(void* const* d_in, const int* in_sizes, int n_in,
                              void* d_out, int out_size) {
    const float* x = (const float*)d_in[0];
    float* out = (float*)d_out;
    (void)in_sizes; (void)n_in; (void)out_size;

    static bool attr_done = false;
    if (!attr_done) {
        cudaFuncSetAttribute(k2_proj, cudaFuncAttributeMaxDynamicSharedMemorySize, K2_SMEM_BYTES);
        cudaFuncSetAttribute(k4_attn, cudaFuncAttributeMaxDynamicSharedMemorySize, K4_SMEM_BYTES);
        attr_done = true;
    }

    k1_build<<<(NB * LVAL + 255) / 256, 256>>>();
    k2_proj<<<dim3(NROWS / 128, KSPLIT), 256, K2_SMEM_BYTES>>>(x);
    k3_softmax<<<NROWS / 8, 256>>>();
    k4_attn<<<dim3(LVAL / 128, NROWS / 64), 256, K4_SMEM_BYTES>>>(x, out);
}